// round 2
// baseline (speedup 1.0000x reference)
#include <cuda_runtime.h>
#include <math.h>

#define D_MODEL 1024
#define NHEAD   16
#define DHEAD   64
#define BATCH   2
#define SEQ     2048
#define M_TOTAL (BATCH*SEQ)

// Scratch (allocation-free rule: __device__ globals)
__device__ float g_q[BATCH*NHEAD*SEQ*DHEAD];
__device__ float g_k[BATCH*NHEAD*SEQ*DHEAD];
__device__ float g_v[BATCH*NHEAD*SEQ*DHEAD];
__device__ float g_attn[BATCH*SEQ*D_MODEL];

// ---------------------------------------------------------------------------
// Kernel 1: fused QKV projection (out = X @ W^T) + RoPE epilogue for Q,K.
// Tile 128x128, K-tile 16, 256 threads, 8x8 per thread.
// blockIdx.z selects {Q,K,V}.
// ---------------------------------------------------------------------------
__global__ void __launch_bounds__(256, 2) qkv_rope_kernel(
    const float* __restrict__ X,
    const float* __restrict__ Wq,
    const float* __restrict__ Wk,
    const float* __restrict__ Wv,
    const int*   __restrict__ pos)
{
    __shared__ float As[16][128];
    __shared__ float Bs[16][128];

    const int which = blockIdx.z;
    const float* W = (which == 0) ? Wq : ((which == 1) ? Wk : Wv);

    const int tid = threadIdx.x;
    const int tx  = tid & 15;
    const int ty  = tid >> 4;
    const int m0  = blockIdx.y * 128;
    const int n0  = blockIdx.x * 128;

    float acc[8][8];
    #pragma unroll
    for (int i = 0; i < 8; i++)
        #pragma unroll
        for (int j = 0; j < 8; j++) acc[i][j] = 0.f;

    const float* Ap = X + (size_t)m0 * D_MODEL;
    const float* Bp = W + (size_t)n0 * D_MODEL;

    for (int k0 = 0; k0 < D_MODEL; k0 += 16) {
        #pragma unroll
        for (int u = 0; u < 2; u++) {
            int f   = tid + u * 256;
            int row = f >> 2;
            int kq  = (f & 3) << 2;
            float4 va = *(const float4*)(Ap + (size_t)row * D_MODEL + k0 + kq);
            As[kq+0][row] = va.x; As[kq+1][row] = va.y;
            As[kq+2][row] = va.z; As[kq+3][row] = va.w;
            float4 vb = *(const float4*)(Bp + (size_t)row * D_MODEL + k0 + kq);
            Bs[kq+0][row] = vb.x; Bs[kq+1][row] = vb.y;
            Bs[kq+2][row] = vb.z; Bs[kq+3][row] = vb.w;
        }
        __syncthreads();
        #pragma unroll
        for (int kk = 0; kk < 16; kk++) {
            float ra[8], rb[8];
            *(float4*)&ra[0] = *(const float4*)&As[kk][ty*8];
            *(float4*)&ra[4] = *(const float4*)&As[kk][ty*8+4];
            *(float4*)&rb[0] = *(const float4*)&Bs[kk][tx*8];
            *(float4*)&rb[4] = *(const float4*)&Bs[kk][tx*8+4];
            #pragma unroll
            for (int i = 0; i < 8; i++)
                #pragma unroll
                for (int j = 0; j < 8; j++)
                    acc[i][j] = fmaf(ra[i], rb[j], acc[i][j]);
        }
        __syncthreads();
    }

    float* outb = (which == 0) ? g_q : ((which == 1) ? g_k : g_v);

    #pragma unroll
    for (int i = 0; i < 8; i++) {
        int m = m0 + ty*8 + i;
        int b = m >> 11;          // / SEQ
        int s = m & 2047;         // % SEQ
        if (which == 2) {
            #pragma unroll
            for (int j = 0; j < 8; j++) {
                int n  = n0 + tx*8 + j;
                int h  = n >> 6;
                int dh = n & 63;
                outb[(((size_t)(b*NHEAD + h))*SEQ + s)*DHEAD + dh] = acc[i][j];
            }
        } else {
            float fp = (float)pos[s];
            #pragma unroll
            for (int jp = 0; jp < 4; jp++) {
                int n  = n0 + tx*8 + jp*2;   // even
                int h  = n >> 6;
                int dh = n & 63;             // even within head
                // inv_freq = 1 / theta^(dh/64), mirror reference fp32 math
                float inv = 1.0f / powf(10000.0f, (float)dh * (1.0f/64.0f));
                float ang = fp * inv;
                float c, sn;
                sincosf(ang, &sn, &c);
                float x0 = acc[i][jp*2+0];
                float x1 = acc[i][jp*2+1];
                size_t base = (((size_t)(b*NHEAD + h))*SEQ + s)*DHEAD + dh;
                outb[base+0] = x0*c - x1*sn;
                outb[base+1] = x1*c + x0*sn;
            }
        }
    }
}

// ---------------------------------------------------------------------------
// Kernel 2: causal flash attention, fp32. One block per (q-tile 64, b*h).
// 256 threads (16x16), each owns 4x4 of the 64x64 score tile and 4x4 of O.
// smem layout (all pitch 64, total 12288 floats = 48KB static):
//   Qs  [qrow][dh]   -- read broadcast (2 rows/warp) -> <=2-way conflict
//   Kt  [dh][krow]   -- transposed K; QK^T reads consecutive -> conflict-free
//                       (reused as P[qrow][kcol] after scores)
//   Vs  [krow][dh]   -- PV reads consecutive -> conflict-free
// ---------------------------------------------------------------------------
__global__ void __launch_bounds__(256) attn_kernel()
{
    __shared__ float sm[3 * 64 * 64]; // 12288 floats = 49152 bytes
    float* Qs = sm;
    float* Kt = sm + 64*64;           // transposed K, reused as P
    float* Vs = sm + 2*64*64;

    const int tid = threadIdx.x;
    const int tx  = tid & 15;
    const int ty  = tid >> 4;
    const int qt  = blockIdx.x;
    const int bh  = blockIdx.y;
    const int q0  = qt * 64;

    const float* Qg = g_q + (size_t)bh * SEQ * DHEAD;
    const float* Kg = g_k + (size_t)bh * SEQ * DHEAD;
    const float* Vg = g_v + (size_t)bh * SEQ * DHEAD;

    // Load Q tile once (coalesced, row-major)
    #pragma unroll
    for (int u = 0; u < 4; u++) {
        int f   = tid + u*256;
        int row = f >> 4;
        int c   = (f & 15) << 2;
        *(float4*)&Qs[row*64 + c] = *(const float4*)(Qg + (size_t)(q0+row)*DHEAD + c);
    }

    float m_i[4], l_i[4], o[4][4];
    #pragma unroll
    for (int i = 0; i < 4; i++) {
        m_i[i] = -INFINITY; l_i[i] = 0.f;
        #pragma unroll
        for (int j = 0; j < 4; j++) o[i][j] = 0.f;
    }

    const float scale = 0.125f; // 1/sqrt(64)

    for (int kt = 0; kt <= qt; kt++) {
        const int k0 = kt * 64;
        __syncthreads(); // prior iter's P/V reads (and Q load) done before overwrite

        // K: lanes span rows -> transposed store is conflict-free.
        // gmem reads are 256B-strided float4s (L2-resident tiles, acceptable).
        #pragma unroll
        for (int u = 0; u < 4; u++) {
            int f   = tid + u*256;
            int row = f & 63;           // lanes consecutive rows
            int c   = (f >> 6) << 2;    // dh chunk, fixed per warp
            float4 kv = *(const float4*)(Kg + (size_t)(k0+row)*DHEAD + c);
            Kt[(c+0)*64 + row] = kv.x;
            Kt[(c+1)*64 + row] = kv.y;
            Kt[(c+2)*64 + row] = kv.z;
            Kt[(c+3)*64 + row] = kv.w;
        }
        // V: coalesced row-major
        #pragma unroll
        for (int u = 0; u < 4; u++) {
            int f   = tid + u*256;
            int row = f >> 4;
            int c   = (f & 15) << 2;
            *(float4*)&Vs[row*64 + c] = *(const float4*)(Vg + (size_t)(k0+row)*DHEAD + c);
        }
        __syncthreads();

        // S = Q @ K^T  (Kt read: consecutive lanes -> conflict-free)
        float sc[4][4] = {};
        #pragma unroll 8
        for (int kk = 0; kk < 64; kk++) {
            float rq[4], rk[4];
            #pragma unroll
            for (int i = 0; i < 4; i++) rq[i] = Qs[(ty*4+i)*64 + kk];
            #pragma unroll
            for (int j = 0; j < 4; j++) rk[j] = Kt[kk*64 + tx*4 + j];
            #pragma unroll
            for (int i = 0; i < 4; i++)
                #pragma unroll
                for (int j = 0; j < 4; j++)
                    sc[i][j] = fmaf(rq[i], rk[j], sc[i][j]);
        }

        if (kt == qt) {
            #pragma unroll
            for (int i = 0; i < 4; i++)
                #pragma unroll
                for (int j = 0; j < 4; j++)
                    sc[i][j] = (tx*4+j <= ty*4+i) ? sc[i][j]*scale : -INFINITY;
        } else {
            #pragma unroll
            for (int i = 0; i < 4; i++)
                #pragma unroll
                for (int j = 0; j < 4; j++)
                    sc[i][j] *= scale;
        }

        __syncthreads(); // all QK^T reads of Kt done before P overwrites it

        // Online softmax; write P (row-major [qrow][kcol]) into Kt region
        #pragma unroll
        for (int i = 0; i < 4; i++) {
            float mloc = fmaxf(fmaxf(sc[i][0], sc[i][1]), fmaxf(sc[i][2], sc[i][3]));
            #pragma unroll
            for (int off = 8; off; off >>= 1)
                mloc = fmaxf(mloc, __shfl_xor_sync(0xffffffffu, mloc, off));
            float mnew  = fmaxf(m_i[i], mloc);
            float alpha = expf(m_i[i] - mnew);
            float rs = 0.f;
            #pragma unroll
            for (int j = 0; j < 4; j++) {
                float p = expf(sc[i][j] - mnew);
                Kt[(ty*4+i)*64 + tx*4 + j] = p;
                rs += p;
            }
            #pragma unroll
            for (int off = 8; off; off >>= 1)
                rs += __shfl_xor_sync(0xffffffffu, rs, off);
            l_i[i] = l_i[i]*alpha + rs;
            m_i[i] = mnew;
            #pragma unroll
            for (int j = 0; j < 4; j++) o[i][j] *= alpha;
        }
        __syncthreads();

        // O += P @ V  (P read broadcast, V read consecutive -> conflict-free)
        #pragma unroll 8
        for (int kk = 0; kk < 64; kk++) {
            float rp[4], rv[4];
            #pragma unroll
            for (int i = 0; i < 4; i++) rp[i] = Kt[(ty*4+i)*64 + kk];
            #pragma unroll
            for (int j = 0; j < 4; j++) rv[j] = Vs[kk*64 + tx*4 + j];
            #pragma unroll
            for (int i = 0; i < 4; i++)
                #pragma unroll
                for (int j = 0; j < 4; j++)
                    o[i][j] = fmaf(rp[i], rv[j], o[i][j]);
        }
    }

    const int b = bh >> 4;
    const int h = bh & 15;
    #pragma unroll
    for (int i = 0; i < 4; i++) {
        int s = q0 + ty*4 + i;
        float invl = 1.0f / l_i[i];
        #pragma unroll
        for (int j = 0; j < 4; j++)
            g_attn[((size_t)(b*SEQ + s))*D_MODEL + h*DHEAD + tx*4 + j] = o[i][j]*invl;
    }
}

// ---------------------------------------------------------------------------
// Kernel 3: output projection (d_out = attn @ Wo^T), same GEMM as kernel 1.
// ---------------------------------------------------------------------------
__global__ void __launch_bounds__(256, 2) out_proj_kernel(
    const float* __restrict__ Wo, float* __restrict__ out)
{
    __shared__ float As[16][128];
    __shared__ float Bs[16][128];

    const int tid = threadIdx.x;
    const int tx  = tid & 15;
    const int ty  = tid >> 4;
    const int m0  = blockIdx.y * 128;
    const int n0  = blockIdx.x * 128;

    float acc[8][8];
    #pragma unroll
    for (int i = 0; i < 8; i++)
        #pragma unroll
        for (int j = 0; j < 8; j++) acc[i][j] = 0.f;

    const float* Ap = g_attn + (size_t)m0 * D_MODEL;
    const float* Bp = Wo     + (size_t)n0 * D_MODEL;

    for (int k0 = 0; k0 < D_MODEL; k0 += 16) {
        #pragma unroll
        for (int u = 0; u < 2; u++) {
            int f   = tid + u * 256;
            int row = f >> 2;
            int kq  = (f & 3) << 2;
            float4 va = *(const float4*)(Ap + (size_t)row * D_MODEL + k0 + kq);
            As[kq+0][row] = va.x; As[kq+1][row] = va.y;
            As[kq+2][row] = va.z; As[kq+3][row] = va.w;
            float4 vb = *(const float4*)(Bp + (size_t)row * D_MODEL + k0 + kq);
            Bs[kq+0][row] = vb.x; Bs[kq+1][row] = vb.y;
            Bs[kq+2][row] = vb.z; Bs[kq+3][row] = vb.w;
        }
        __syncthreads();
        #pragma unroll
        for (int kk = 0; kk < 16; kk++) {
            float ra[8], rb[8];
            *(float4*)&ra[0] = *(const float4*)&As[kk][ty*8];
            *(float4*)&ra[4] = *(const float4*)&As[kk][ty*8+4];
            *(float4*)&rb[0] = *(const float4*)&Bs[kk][tx*8];
            *(float4*)&rb[4] = *(const float4*)&Bs[kk][tx*8+4];
            #pragma unroll
            for (int i = 0; i < 8; i++)
                #pragma unroll
                for (int j = 0; j < 8; j++)
                    acc[i][j] = fmaf(ra[i], rb[j], acc[i][j]);
        }
        __syncthreads();
    }

    #pragma unroll
    for (int i = 0; i < 8; i++) {
        size_t m = m0 + ty*8 + i;
        float4 v0 = make_float4(acc[i][0], acc[i][1], acc[i][2], acc[i][3]);
        float4 v1 = make_float4(acc[i][4], acc[i][5], acc[i][6], acc[i][7]);
        *(float4*)(out + m * D_MODEL + n0 + tx*8 + 0) = v0;
        *(float4*)(out + m * D_MODEL + n0 + tx*8 + 4) = v1;
    }
}

// ---------------------------------------------------------------------------
extern "C" void kernel_launch(void* const* d_in, const int* in_sizes, int n_in,
                              void* d_out, int out_size)
{
    const float* X   = (const float*)d_in[0];
    const int*   pos = (const int*)  d_in[1];
    const float* wq  = (const float*)d_in[2];
    const float* wk  = (const float*)d_in[3];
    const float* wv  = (const float*)d_in[4];
    const float* wo  = (const float*)d_in[5];
    float* out = (float*)d_out;

    dim3 gProj(D_MODEL/128, M_TOTAL/128, 3);         // (8, 32, 3)
    qkv_rope_kernel<<<gProj, 256>>>(X, wq, wk, wv, pos);

    dim3 gAttn(SEQ/64, BATCH*NHEAD);                 // (32, 32)
    attn_kernel<<<gAttn, 256>>>();

    dim3 gOut(D_MODEL/128, M_TOTAL/128);             // (8, 32)
    out_proj_kernel<<<gOut, 256>>>(wo, out);
}

// round 4
// speedup vs baseline: 1.6531x; 1.6531x over previous
#include <cuda_runtime.h>
#include <math.h>
#include <cstdint>

#define D_MODEL 1024
#define NHEAD   16
#define DHEAD   64
#define BATCH   2
#define SEQ     2048
#define M_TOTAL (BATCH*SEQ)

// Scratch (allocation-free rule: __device__ globals).
// q/k/v ROW-MAJOR [b*s][h*64+dh]
__device__ float g_q[M_TOTAL*D_MODEL];
__device__ float g_k[M_TOTAL*D_MODEL];
__device__ float g_v[M_TOTAL*D_MODEL];
__device__ float g_attn[M_TOTAL*D_MODEL];

__device__ __forceinline__ uint32_t f2tf32(float x) {
    uint32_t r; asm("cvt.rna.tf32.f32 %0, %1;" : "=r"(r) : "f"(x));
    return r;
}

__device__ __forceinline__ void mma_tf32(float c[4], const uint32_t a[4], const uint32_t b[2]) {
    asm volatile(
        "mma.sync.aligned.m16n8k8.row.col.f32.tf32.tf32.f32 "
        "{%0,%1,%2,%3}, {%4,%5,%6,%7}, {%8,%9}, {%0,%1,%2,%3};"
        : "+f"(c[0]), "+f"(c[1]), "+f"(c[2]), "+f"(c[3])
        : "r"(a[0]), "r"(a[1]), "r"(a[2]), "r"(a[3]), "r"(b[0]), "r"(b[1]));
}

// ---------------------------------------------------------------------------
// tf32 mma.sync GEMM: out[m][n] = sum_k A[m][k] * W[n][k].
// CTA tile 128x128, K-tile 32. 8 warps (4 in M, 2 in N), warp tile 32x64.
// smem pitch 36 floats -> conflict-free fragment reads & float4 writes.
// mode: 0=Q(+rope) 1=K(+rope) 2=V 3=out-projection
// ---------------------------------------------------------------------------
#define PITCH 36

__global__ void __launch_bounds__(256, 2) gemm_tf32_kernel(
    const float* __restrict__ X,
    const float* __restrict__ Wq, const float* __restrict__ Wk,
    const float* __restrict__ Wv, const float* __restrict__ Wo,
    const int*   __restrict__ pos,
    float* __restrict__ dout,
    int mode_base)
{
    __shared__ __align__(16) uint32_t As[128*PITCH];
    __shared__ __align__(16) uint32_t Bs[128*PITCH];

    const int mode = mode_base + blockIdx.z;
    const float* A = (mode == 3) ? g_attn : X;
    const float* W = (mode == 0) ? Wq : (mode == 1) ? Wk : (mode == 2) ? Wv : Wo;
    float* out = (mode == 0) ? g_q : (mode == 1) ? g_k : (mode == 2) ? g_v : dout;
    const bool rope = (mode <= 1);

    const int tid  = threadIdx.x;
    const int warp = tid >> 5;
    const int lane = tid & 31;
    const int gr   = lane >> 2;   // group row / group col
    const int tig  = lane & 3;    // thread in group
    const int wm   = warp & 3;    // warp m block (32 rows)
    const int wn   = warp >> 2;   // warp n block (64 cols)
    const int m0   = blockIdx.y * 128;
    const int n0   = blockIdx.x * 128;

    float acc[2][8][4];
    #pragma unroll
    for (int mf = 0; mf < 2; mf++)
        #pragma unroll
        for (int nf = 0; nf < 8; nf++)
            #pragma unroll
            for (int c = 0; c < 4; c++) acc[mf][nf][c] = 0.f;

    const float* Ap = A + (size_t)m0 * D_MODEL;
    const float* Wp = W + (size_t)n0 * D_MODEL;

    // loader mapping: f = tid + u*256 in 0..1023; row = f>>3, kq = (f&7)*4
    const int lrow = tid >> 3;
    const int lkq  = (tid & 7) << 2;

    for (int k0 = 0; k0 < D_MODEL; k0 += 32) {
        __syncthreads();
        #pragma unroll
        for (int u = 0; u < 4; u++) {
            int row = lrow + u * 32;
            float4 va = *(const float4*)(Ap + (size_t)row * D_MODEL + k0 + lkq);
            uint4 ua = make_uint4(f2tf32(va.x), f2tf32(va.y), f2tf32(va.z), f2tf32(va.w));
            *(uint4*)&As[row * PITCH + lkq] = ua;
            float4 vb = *(const float4*)(Wp + (size_t)row * D_MODEL + k0 + lkq);
            uint4 ub = make_uint4(f2tf32(vb.x), f2tf32(vb.y), f2tf32(vb.z), f2tf32(vb.w));
            *(uint4*)&Bs[row * PITCH + lkq] = ub;
        }
        __syncthreads();

        #pragma unroll
        for (int ks = 0; ks < 4; ks++) {
            const int kb = ks * 8;
            uint32_t b[8][2];
            #pragma unroll
            for (int nf = 0; nf < 8; nf++) {
                int n = wn*64 + nf*8 + gr;
                b[nf][0] = Bs[n * PITCH + kb + tig];
                b[nf][1] = Bs[n * PITCH + kb + tig + 4];
            }
            uint32_t a[2][4];
            #pragma unroll
            for (int mf = 0; mf < 2; mf++) {
                int m = wm*32 + mf*16 + gr;
                a[mf][0] = As[m * PITCH + kb + tig];
                a[mf][1] = As[(m+8) * PITCH + kb + tig];
                a[mf][2] = As[m * PITCH + kb + tig + 4];
                a[mf][3] = As[(m+8) * PITCH + kb + tig + 4];
            }
            #pragma unroll
            for (int mf = 0; mf < 2; mf++)
                #pragma unroll
                for (int nf = 0; nf < 8; nf++)
                    mma_tf32(acc[mf][nf], a[mf], b[nf]);
        }
    }

    // Epilogue. C frag: c0,c1 = row gr, cols 2tig,2tig+1; c2,c3 = row gr+8.
    float invf[8];
    if (rope) {
        #pragma unroll
        for (int nf = 0; nf < 8; nf++) {
            int dh = (nf*8 + 2*tig) & 63;
            invf[nf] = 1.0f / powf(10000.0f, (float)dh * (1.0f/64.0f));
        }
    }

    #pragma unroll
    for (int mf = 0; mf < 2; mf++) {
        int m_lo = m0 + wm*32 + mf*16 + gr;
        int m_hi = m_lo + 8;
        float fp_lo = 0.f, fp_hi = 0.f;
        if (rope) {
            fp_lo = (float)pos[m_lo & (SEQ-1)];
            fp_hi = (float)pos[m_hi & (SEQ-1)];
        }
        #pragma unroll
        for (int nf = 0; nf < 8; nf++) {
            int n = n0 + wn*64 + nf*8 + 2*tig;
            float v0 = acc[mf][nf][0], v1 = acc[mf][nf][1];
            float v2 = acc[mf][nf][2], v3 = acc[mf][nf][3];
            if (rope) {
                float c0, s0, c1, s1;
                sincosf(fp_lo * invf[nf], &s0, &c0);
                sincosf(fp_hi * invf[nf], &s1, &c1);
                float r0 = v0*c0 - v1*s0, r1 = v1*c0 + v0*s0;
                float r2 = v2*c1 - v3*s1, r3 = v3*c1 + v2*s1;
                v0 = r0; v1 = r1; v2 = r2; v3 = r3;
            }
            *(float2*)(out + (size_t)m_lo * D_MODEL + n) = make_float2(v0, v1);
            *(float2*)(out + (size_t)m_hi * D_MODEL + n) = make_float2(v2, v3);
        }
    }
}

// ---------------------------------------------------------------------------
// Causal flash attention, fp32 SIMT. q/k/v row-major [b*s][h*64+dh].
// ---------------------------------------------------------------------------
__global__ void __launch_bounds__(256) attn_kernel()
{
    __shared__ float sm[3 * 64 * 64]; // 48KB
    float* Qs = sm;
    float* Kt = sm + 64*64;           // transposed K, reused as P
    float* Vs = sm + 2*64*64;

    const int tid = threadIdx.x;
    const int tx  = tid & 15;
    const int ty  = tid >> 4;
    const int qt  = blockIdx.x;
    const int bh  = blockIdx.y;
    const int q0  = qt * 64;
    const int b   = bh >> 4;
    const int h   = bh & 15;

    const float* Qg = g_q + (size_t)b*SEQ*D_MODEL + h*DHEAD;
    const float* Kg = g_k + (size_t)b*SEQ*D_MODEL + h*DHEAD;
    const float* Vg = g_v + (size_t)b*SEQ*D_MODEL + h*DHEAD;

    #pragma unroll
    for (int u = 0; u < 4; u++) {
        int f   = tid + u*256;
        int row = f >> 4;
        int c   = (f & 15) << 2;
        *(float4*)&Qs[row*64 + c] = *(const float4*)(Qg + (size_t)(q0+row)*D_MODEL + c);
    }

    float m_i[4], l_i[4], o[4][4];
    #pragma unroll
    for (int i = 0; i < 4; i++) {
        m_i[i] = -INFINITY; l_i[i] = 0.f;
        #pragma unroll
        for (int j = 0; j < 4; j++) o[i][j] = 0.f;
    }

    const float scale = 0.125f;

    for (int kt = 0; kt <= qt; kt++) {
        const int k0 = kt * 64;
        __syncthreads();

        #pragma unroll
        for (int u = 0; u < 4; u++) {
            int f   = tid + u*256;
            int row = f & 63;
            int c   = (f >> 6) << 2;
            float4 kv = *(const float4*)(Kg + (size_t)(k0+row)*D_MODEL + c);
            Kt[(c+0)*64 + row] = kv.x;
            Kt[(c+1)*64 + row] = kv.y;
            Kt[(c+2)*64 + row] = kv.z;
            Kt[(c+3)*64 + row] = kv.w;
        }
        #pragma unroll
        for (int u = 0; u < 4; u++) {
            int f   = tid + u*256;
            int row = f >> 4;
            int c   = (f & 15) << 2;
            *(float4*)&Vs[row*64 + c] = *(const float4*)(Vg + (size_t)(k0+row)*D_MODEL + c);
        }
        __syncthreads();

        float sc[4][4] = {};
        #pragma unroll 8
        for (int kk = 0; kk < 64; kk++) {
            float rq[4], rk[4];
            #pragma unroll
            for (int i = 0; i < 4; i++) rq[i] = Qs[(ty*4+i)*64 + kk];
            #pragma unroll
            for (int j = 0; j < 4; j++) rk[j] = Kt[kk*64 + tx*4 + j];
            #pragma unroll
            for (int i = 0; i < 4; i++)
                #pragma unroll
                for (int j = 0; j < 4; j++)
                    sc[i][j] = fmaf(rq[i], rk[j], sc[i][j]);
        }

        if (kt == qt) {
            #pragma unroll
            for (int i = 0; i < 4; i++)
                #pragma unroll
                for (int j = 0; j < 4; j++)
                    sc[i][j] = (tx*4+j <= ty*4+i) ? sc[i][j]*scale : -INFINITY;
        } else {
            #pragma unroll
            for (int i = 0; i < 4; i++)
                #pragma unroll
                for (int j = 0; j < 4; j++)
                    sc[i][j] *= scale;
        }

        __syncthreads();

        #pragma unroll
        for (int i = 0; i < 4; i++) {
            float mloc = fmaxf(fmaxf(sc[i][0], sc[i][1]), fmaxf(sc[i][2], sc[i][3]));
            #pragma unroll
            for (int off = 8; off; off >>= 1)
                mloc = fmaxf(mloc, __shfl_xor_sync(0xffffffffu, mloc, off));
            float mnew  = fmaxf(m_i[i], mloc);
            float alpha = expf(m_i[i] - mnew);
            float rs = 0.f;
            #pragma unroll
            for (int j = 0; j < 4; j++) {
                float p = expf(sc[i][j] - mnew);
                Kt[(ty*4+i)*64 + tx*4 + j] = p;
                rs += p;
            }
            #pragma unroll
            for (int off = 8; off; off >>= 1)
                rs += __shfl_xor_sync(0xffffffffu, rs, off);
            l_i[i] = l_i[i]*alpha + rs;
            m_i[i] = mnew;
            #pragma unroll
            for (int j = 0; j < 4; j++) o[i][j] *= alpha;
        }
        __syncthreads();

        #pragma unroll 8
        for (int kk = 0; kk < 64; kk++) {
            float rp[4], rv[4];
            #pragma unroll
            for (int i = 0; i < 4; i++) rp[i] = Kt[(ty*4+i)*64 + kk];
            #pragma unroll
            for (int j = 0; j < 4; j++) rv[j] = Vs[kk*64 + tx*4 + j];
            #pragma unroll
            for (int i = 0; i < 4; i++)
                #pragma unroll
                for (int j = 0; j < 4; j++)
                    o[i][j] = fmaf(rp[i], rv[j], o[i][j]);
        }
    }

    #pragma unroll
    for (int i = 0; i < 4; i++) {
        int s = q0 + ty*4 + i;
        float invl = 1.0f / l_i[i];
        #pragma unroll
        for (int j = 0; j < 4; j++)
            g_attn[((size_t)(b*SEQ + s))*D_MODEL + h*DHEAD + tx*4 + j] = o[i][j]*invl;
    }
}

// ---------------------------------------------------------------------------
extern "C" void kernel_launch(void* const* d_in, const int* in_sizes, int n_in,
                              void* d_out, int out_size)
{
    const float* X   = (const float*)d_in[0];
    const int*   pos = (const int*)  d_in[1];
    const float* wq  = (const float*)d_in[2];
    const float* wk  = (const float*)d_in[3];
    const float* wv  = (const float*)d_in[4];
    const float* wo  = (const float*)d_in[5];
    float* out = (float*)d_out;

    dim3 gQKV(D_MODEL/128, M_TOTAL/128, 3);          // (8, 32, 3)
    gemm_tf32_kernel<<<gQKV, 256>>>(X, wq, wk, wv, wo, pos, out, 0);

    dim3 gAttn(SEQ/64, BATCH*NHEAD);                 // (32, 32)
    attn_kernel<<<gAttn, 256>>>();

    dim3 gOut(D_MODEL/128, M_TOTAL/128, 1);          // (8, 32)
    gemm_tf32_kernel<<<gOut, 256>>>(X, wq, wk, wv, wo, pos, out, 3);
}

// round 5
// speedup vs baseline: 2.8074x; 1.6982x over previous
#include <cuda_runtime.h>
#include <math.h>
#include <cstdint>

#define D_MODEL 1024
#define NHEAD   16
#define DHEAD   64
#define BATCH   2
#define SEQ     2048
#define M_TOTAL (BATCH*SEQ)

// Scratch (allocation-free rule: __device__ globals).
__device__ float g_q[M_TOTAL*D_MODEL];
__device__ float g_k[M_TOTAL*D_MODEL];
__device__ float g_v[M_TOTAL*D_MODEL];
__device__ float g_attn[M_TOTAL*D_MODEL];

__device__ __forceinline__ uint32_t f2tf32(float x) {
    uint32_t r; asm("cvt.rna.tf32.f32 %0, %1;" : "=r"(r) : "f"(x));
    return r;
}

__device__ __forceinline__ void mma_tf32(float c[4], const uint32_t a[4], const uint32_t b[2]) {
    asm volatile(
        "mma.sync.aligned.m16n8k8.row.col.f32.tf32.tf32.f32 "
        "{%0,%1,%2,%3}, {%4,%5,%6,%7}, {%8,%9}, {%0,%1,%2,%3};"
        : "+f"(c[0]), "+f"(c[1]), "+f"(c[2]), "+f"(c[3])
        : "r"(a[0]), "r"(a[1]), "r"(a[2]), "r"(a[3]), "r"(b[0]), "r"(b[1]));
}

// ---------------------------------------------------------------------------
// tf32 mma.sync GEMM: out[m][n] = sum_k A[m][k] * W[n][k]. (unchanged from R4)
// ---------------------------------------------------------------------------
#define PITCH 36

__global__ void __launch_bounds__(256, 2) gemm_tf32_kernel(
    const float* __restrict__ X,
    const float* __restrict__ Wq, const float* __restrict__ Wk,
    const float* __restrict__ Wv, const float* __restrict__ Wo,
    const int*   __restrict__ pos,
    float* __restrict__ dout,
    int mode_base)
{
    __shared__ __align__(16) uint32_t As[128*PITCH];
    __shared__ __align__(16) uint32_t Bs[128*PITCH];

    const int mode = mode_base + blockIdx.z;
    const float* A = (mode == 3) ? g_attn : X;
    const float* W = (mode == 0) ? Wq : (mode == 1) ? Wk : (mode == 2) ? Wv : Wo;
    float* out = (mode == 0) ? g_q : (mode == 1) ? g_k : (mode == 2) ? g_v : dout;
    const bool rope = (mode <= 1);

    const int tid  = threadIdx.x;
    const int warp = tid >> 5;
    const int lane = tid & 31;
    const int gr   = lane >> 2;
    const int tig  = lane & 3;
    const int wm   = warp & 3;
    const int wn   = warp >> 2;
    const int m0   = blockIdx.y * 128;
    const int n0   = blockIdx.x * 128;

    float acc[2][8][4];
    #pragma unroll
    for (int mf = 0; mf < 2; mf++)
        #pragma unroll
        for (int nf = 0; nf < 8; nf++)
            #pragma unroll
            for (int c = 0; c < 4; c++) acc[mf][nf][c] = 0.f;

    const float* Ap = A + (size_t)m0 * D_MODEL;
    const float* Wp = W + (size_t)n0 * D_MODEL;

    const int lrow = tid >> 3;
    const int lkq  = (tid & 7) << 2;

    for (int k0 = 0; k0 < D_MODEL; k0 += 32) {
        __syncthreads();
        #pragma unroll
        for (int u = 0; u < 4; u++) {
            int row = lrow + u * 32;
            float4 va = *(const float4*)(Ap + (size_t)row * D_MODEL + k0 + lkq);
            uint4 ua = make_uint4(f2tf32(va.x), f2tf32(va.y), f2tf32(va.z), f2tf32(va.w));
            *(uint4*)&As[row * PITCH + lkq] = ua;
            float4 vb = *(const float4*)(Wp + (size_t)row * D_MODEL + k0 + lkq);
            uint4 ub = make_uint4(f2tf32(vb.x), f2tf32(vb.y), f2tf32(vb.z), f2tf32(vb.w));
            *(uint4*)&Bs[row * PITCH + lkq] = ub;
        }
        __syncthreads();

        #pragma unroll
        for (int ks = 0; ks < 4; ks++) {
            const int kb = ks * 8;
            uint32_t b[8][2];
            #pragma unroll
            for (int nf = 0; nf < 8; nf++) {
                int n = wn*64 + nf*8 + gr;
                b[nf][0] = Bs[n * PITCH + kb + tig];
                b[nf][1] = Bs[n * PITCH + kb + tig + 4];
            }
            uint32_t a[2][4];
            #pragma unroll
            for (int mf = 0; mf < 2; mf++) {
                int m = wm*32 + mf*16 + gr;
                a[mf][0] = As[m * PITCH + kb + tig];
                a[mf][1] = As[(m+8) * PITCH + kb + tig];
                a[mf][2] = As[m * PITCH + kb + tig + 4];
                a[mf][3] = As[(m+8) * PITCH + kb + tig + 4];
            }
            #pragma unroll
            for (int mf = 0; mf < 2; mf++)
                #pragma unroll
                for (int nf = 0; nf < 8; nf++)
                    mma_tf32(acc[mf][nf], a[mf], b[nf]);
        }
    }

    float invf[8];
    if (rope) {
        #pragma unroll
        for (int nf = 0; nf < 8; nf++) {
            int dh = (nf*8 + 2*tig) & 63;
            invf[nf] = 1.0f / powf(10000.0f, (float)dh * (1.0f/64.0f));
        }
    }

    #pragma unroll
    for (int mf = 0; mf < 2; mf++) {
        int m_lo = m0 + wm*32 + mf*16 + gr;
        int m_hi = m_lo + 8;
        float fp_lo = 0.f, fp_hi = 0.f;
        if (rope) {
            fp_lo = (float)pos[m_lo & (SEQ-1)];
            fp_hi = (float)pos[m_hi & (SEQ-1)];
        }
        #pragma unroll
        for (int nf = 0; nf < 8; nf++) {
            int n = n0 + wn*64 + nf*8 + 2*tig;
            float v0 = acc[mf][nf][0], v1 = acc[mf][nf][1];
            float v2 = acc[mf][nf][2], v3 = acc[mf][nf][3];
            if (rope) {
                float c0, s0, c1, s1;
                sincosf(fp_lo * invf[nf], &s0, &c0);
                sincosf(fp_hi * invf[nf], &s1, &c1);
                float r0 = v0*c0 - v1*s0, r1 = v1*c0 + v0*s0;
                float r2 = v2*c1 - v3*s1, r3 = v3*c1 + v2*s1;
                v0 = r0; v1 = r1; v2 = r2; v3 = r3;
            }
            *(float2*)(out + (size_t)m_lo * D_MODEL + n) = make_float2(v0, v1);
            *(float2*)(out + (size_t)m_hi * D_MODEL + n) = make_float2(v2, v3);
        }
    }
}

// ---------------------------------------------------------------------------
// Flash attention with tf32 mma.sync + error-compensated splits.
// CTA: 64 q-rows, 4 warps (16 rows each). K-tile 64.
// QK^T: 3-MMA split (near-exact). PV: 2-MMA split (P exact, V single-rounded).
// smem: sK[64][68] fp32 (reused for P), sV[64][72] tf32-prerounded = 35.8KB.
// ---------------------------------------------------------------------------
#define PK  68
#define PVP 72

__global__ void __launch_bounds__(128) attn_mma_kernel()
{
    __shared__ float sK[64*PK];   // K tile fp32; reused as P tile
    __shared__ float sV[64*PVP];  // V tile, pre-rounded to tf32

    const int tid  = threadIdx.x;
    const int warp = tid >> 5;
    const int lane = tid & 31;
    const int gr   = lane >> 2;
    const int tig  = lane & 3;
    const int qt   = blockIdx.x;
    const int bh   = blockIdx.y;
    const int q0   = qt * 64;
    const int b    = bh >> 4;
    const int h    = bh & 15;

    const float* Qg = g_q + (size_t)b*SEQ*D_MODEL + h*DHEAD;
    const float* Kg = g_k + (size_t)b*SEQ*D_MODEL + h*DHEAD;
    const float* Vg = g_v + (size_t)b*SEQ*D_MODEL + h*DHEAD;

    // ---- Stage Q (scaled by exact 1/8) into sK, then extract split a-frags
    #pragma unroll
    for (int u = 0; u < 8; u++) {
        int f   = tid + u*128;
        int row = f >> 4;
        int c   = (f & 15) << 2;
        float4 q = *(const float4*)(Qg + (size_t)(q0+row)*D_MODEL + c);
        q.x *= 0.125f; q.y *= 0.125f; q.z *= 0.125f; q.w *= 0.125f;
        *(float4*)&sK[row*PK + c] = q;
    }
    __syncthreads();

    const int r0l = warp*16 + gr;   // local q row (c0/c1)
    const int r1l = r0l + 8;        // local q row (c2/c3)

    uint32_t qh[8][4], ql[8][4];
    #pragma unroll
    for (int kb = 0; kb < 8; kb++) {
        float f0 = sK[r0l*PK + kb*8 + tig];
        float f1 = sK[r1l*PK + kb*8 + tig];
        float f2 = sK[r0l*PK + kb*8 + tig + 4];
        float f3 = sK[r1l*PK + kb*8 + tig + 4];
        qh[kb][0] = f2tf32(f0); ql[kb][0] = f2tf32(f0 - __uint_as_float(qh[kb][0]));
        qh[kb][1] = f2tf32(f1); ql[kb][1] = f2tf32(f1 - __uint_as_float(qh[kb][1]));
        qh[kb][2] = f2tf32(f2); ql[kb][2] = f2tf32(f2 - __uint_as_float(qh[kb][2]));
        qh[kb][3] = f2tf32(f3); ql[kb][3] = f2tf32(f3 - __uint_as_float(qh[kb][3]));
    }

    float m0 = -INFINITY, m1 = -INFINITY, l0 = 0.f, l1 = 0.f;
    float acc[8][4];
    #pragma unroll
    for (int nf = 0; nf < 8; nf++)
        #pragma unroll
        for (int c = 0; c < 4; c++) acc[nf][c] = 0.f;

    for (int kt = 0; kt <= qt; kt++) {
        const int k0 = kt * 64;
        __syncthreads();  // prior P/V reads (or Q staging) complete

        // Load K (fp32) and V (pre-rounded tf32)
        #pragma unroll
        for (int u = 0; u < 8; u++) {
            int f   = tid + u*128;
            int row = f >> 4;
            int c   = (f & 15) << 2;
            *(float4*)&sK[row*PK + c] = *(const float4*)(Kg + (size_t)(k0+row)*D_MODEL + c);
            float4 v = *(const float4*)(Vg + (size_t)(k0+row)*D_MODEL + c);
            v.x = __uint_as_float(f2tf32(v.x));
            v.y = __uint_as_float(f2tf32(v.y));
            v.z = __uint_as_float(f2tf32(v.z));
            v.w = __uint_as_float(f2tf32(v.w));
            *(float4*)&sV[row*PVP + c] = v;
        }
        __syncthreads();

        // S = Q @ K^T  (3-MMA split per fragment)
        float s[8][4];
        #pragma unroll
        for (int nf = 0; nf < 8; nf++)
            #pragma unroll
            for (int c = 0; c < 4; c++) s[nf][c] = 0.f;

        #pragma unroll
        for (int kb = 0; kb < 8; kb++) {
            #pragma unroll
            for (int nf = 0; nf < 8; nf++) {
                float b0f = sK[(nf*8+gr)*PK + kb*8 + tig];
                float b1f = sK[(nf*8+gr)*PK + kb*8 + tig + 4];
                uint32_t bhv[2], blv[2];
                bhv[0] = f2tf32(b0f); blv[0] = f2tf32(b0f - __uint_as_float(bhv[0]));
                bhv[1] = f2tf32(b1f); blv[1] = f2tf32(b1f - __uint_as_float(bhv[1]));
                mma_tf32(s[nf], qh[kb], bhv);
                mma_tf32(s[nf], ql[kb], bhv);
                mma_tf32(s[nf], qh[kb], blv);
            }
        }

        // Causal mask on diagonal tile (k0 == q0)
        if (kt == qt) {
            #pragma unroll
            for (int nf = 0; nf < 8; nf++) {
                int cl = nf*8 + 2*tig;
                if (cl   > r0l) s[nf][0] = -INFINITY;
                if (cl+1 > r0l) s[nf][1] = -INFINITY;
                if (cl   > r1l) s[nf][2] = -INFINITY;
                if (cl+1 > r1l) s[nf][3] = -INFINITY;
            }
        }

        // Online softmax (rows r0l, r1l; quad = lanes with same gr)
        float ml0 = -INFINITY, ml1 = -INFINITY;
        #pragma unroll
        for (int nf = 0; nf < 8; nf++) {
            ml0 = fmaxf(ml0, fmaxf(s[nf][0], s[nf][1]));
            ml1 = fmaxf(ml1, fmaxf(s[nf][2], s[nf][3]));
        }
        ml0 = fmaxf(ml0, __shfl_xor_sync(0xffffffffu, ml0, 1));
        ml0 = fmaxf(ml0, __shfl_xor_sync(0xffffffffu, ml0, 2));
        ml1 = fmaxf(ml1, __shfl_xor_sync(0xffffffffu, ml1, 1));
        ml1 = fmaxf(ml1, __shfl_xor_sync(0xffffffffu, ml1, 2));

        float mn0 = fmaxf(m0, ml0), mn1 = fmaxf(m1, ml1);
        float al0 = __expf(m0 - mn0), al1 = __expf(m1 - mn1);
        float rs0 = 0.f, rs1 = 0.f;
        #pragma unroll
        for (int nf = 0; nf < 8; nf++) {
            float p0 = __expf(s[nf][0] - mn0);
            float p1 = __expf(s[nf][1] - mn0);
            float p2 = __expf(s[nf][2] - mn1);
            float p3 = __expf(s[nf][3] - mn1);
            s[nf][0] = p0; s[nf][1] = p1; s[nf][2] = p2; s[nf][3] = p3;
            rs0 += p0 + p1; rs1 += p2 + p3;
        }
        rs0 += __shfl_xor_sync(0xffffffffu, rs0, 1);
        rs0 += __shfl_xor_sync(0xffffffffu, rs0, 2);
        rs1 += __shfl_xor_sync(0xffffffffu, rs1, 1);
        rs1 += __shfl_xor_sync(0xffffffffu, rs1, 2);
        l0 = l0*al0 + rs0; m0 = mn0;
        l1 = l1*al1 + rs1; m1 = mn1;
        #pragma unroll
        for (int nf = 0; nf < 8; nf++) {
            acc[nf][0] *= al0; acc[nf][1] *= al0;
            acc[nf][2] *= al1; acc[nf][3] *= al1;
        }

        __syncthreads(); // all warps done reading sK (b-frags) before P overwrites

        // Store P into sK region (each warp its own 16 rows)
        #pragma unroll
        for (int nf = 0; nf < 8; nf++) {
            *(float2*)&sK[r0l*PK + nf*8 + 2*tig] = make_float2(s[nf][0], s[nf][1]);
            *(float2*)&sK[r1l*PK + nf*8 + 2*tig] = make_float2(s[nf][2], s[nf][3]);
        }
        __syncwarp();

        // O += P @ V  (2-MMA split: P exact, V pre-rounded)
        #pragma unroll
        for (int kb = 0; kb < 8; kb++) {
            float a0f = sK[r0l*PK + kb*8 + tig];
            float a1f = sK[r1l*PK + kb*8 + tig];
            float a2f = sK[r0l*PK + kb*8 + tig + 4];
            float a3f = sK[r1l*PK + kb*8 + tig + 4];
            uint32_t ah[4], al[4];
            ah[0] = f2tf32(a0f); al[0] = f2tf32(a0f - __uint_as_float(ah[0]));
            ah[1] = f2tf32(a1f); al[1] = f2tf32(a1f - __uint_as_float(ah[1]));
            ah[2] = f2tf32(a2f); al[2] = f2tf32(a2f - __uint_as_float(ah[2]));
            ah[3] = f2tf32(a3f); al[3] = f2tf32(a3f - __uint_as_float(ah[3]));
            #pragma unroll
            for (int nf = 0; nf < 8; nf++) {
                uint32_t bb[2];
                bb[0] = __float_as_uint(sV[(kb*8+tig)*PVP + nf*8 + gr]);
                bb[1] = __float_as_uint(sV[(kb*8+tig+4)*PVP + nf*8 + gr]);
                mma_tf32(acc[nf], ah, bb);
                mma_tf32(acc[nf], al, bb);
            }
        }
    }

    // Epilogue
    const float il0 = 1.0f / l0;
    const float il1 = 1.0f / l1;
    const int r0g = q0 + r0l;
    const int r1g = q0 + r1l;
    float* o0 = g_attn + (size_t)(b*SEQ + r0g)*D_MODEL + h*DHEAD;
    float* o1 = g_attn + (size_t)(b*SEQ + r1g)*D_MODEL + h*DHEAD;
    #pragma unroll
    for (int nf = 0; nf < 8; nf++) {
        *(float2*)(o0 + nf*8 + 2*tig) = make_float2(acc[nf][0]*il0, acc[nf][1]*il0);
        *(float2*)(o1 + nf*8 + 2*tig) = make_float2(acc[nf][2]*il1, acc[nf][3]*il1);
    }
}

// ---------------------------------------------------------------------------
extern "C" void kernel_launch(void* const* d_in, const int* in_sizes, int n_in,
                              void* d_out, int out_size)
{
    const float* X   = (const float*)d_in[0];
    const int*   pos = (const int*)  d_in[1];
    const float* wq  = (const float*)d_in[2];
    const float* wk  = (const float*)d_in[3];
    const float* wv  = (const float*)d_in[4];
    const float* wo  = (const float*)d_in[5];
    float* out = (float*)d_out;

    dim3 gQKV(D_MODEL/128, M_TOTAL/128, 3);          // (8, 32, 3)
    gemm_tf32_kernel<<<gQKV, 256>>>(X, wq, wk, wv, wo, pos, out, 0);

    dim3 gAttn(SEQ/64, BATCH*NHEAD);                 // (32, 32)
    attn_mma_kernel<<<gAttn, 128>>>();

    dim3 gOut(D_MODEL/128, M_TOTAL/128, 1);          // (8, 32)
    gemm_tf32_kernel<<<gOut, 256>>>(X, wq, wk, wv, wo, pos, out, 3);
}